// round 17
// baseline (speedup 1.0000x reference)
#include <cuda_runtime.h>
#include <cuda_bf16.h>

#define G 256
#define D 128
#define H 64
#define GPB 2           // graphs per MLP block (128 blocks -> single wave)
#define WARP_FULL 0xffffffffu

// Scratch accumulators (allocation-free rule: __device__ globals).
// Statically zero-initialized -> first call correct; MLP epilogue re-zeroes
// them so every graph replay starts clean.
__device__ float g_sums[G * D];
__device__ float g_counts[G];

// ---------------------------------------------------------------------------
// Kernel 1: streaming segment-sum, single wave (592 CTAs = 4/SM x 148 SMs).
// Work is dealt in 32-row chunks, balanced so every warp gets base or base+1
// chunks (no wave transitions, no ragged per-warp tails). Lane L accumulates
// cols [4L,4L+4) in a float4; atomics only at (rare) segment boundaries.
// ---------------------------------------------------------------------------
__device__ __forceinline__ void flush_seg(int g, int lane, const float4& acc, float cnt) {
    if (g < 0 || g >= G || cnt == 0.0f) return;
    float* s = &g_sums[g * D + lane * 4];
    atomicAdd(s + 0, acc.x);
    atomicAdd(s + 1, acc.y);
    atomicAdd(s + 2, acc.z);
    atomicAdd(s + 3, acc.w);
    if (lane == 0) atomicAdd(&g_counts[g], cnt);
}

__global__ __launch_bounds__(256) void reduce_kernel(
    const float4* __restrict__ x4,      // [N, 32] float4 view of x[N,128]
    const int* __restrict__ batch,      // [N] int32
    int N, int chunks_base, int chunks_rem)
{
    // Let the dependent MLP kernel start placing/staging as SMs free up.
    cudaTriggerProgrammaticLaunchCompletion();

    const int w    = (blockIdx.x * blockDim.x + threadIdx.x) >> 5;
    const int lane = threadIdx.x & 31;

    // balanced chunk range for this warp
    int start_chunk = w * chunks_base + min(w, chunks_rem);
    int n_chunks    = chunks_base + (w < chunks_rem ? 1 : 0);
    int r0 = start_chunk * 32;
    if (r0 >= N || n_chunks == 0) return;
    int r1 = min(N, r0 + n_chunks * 32);

    float4 acc = make_float4(0.f, 0.f, 0.f, 0.f);
    float  cnt = 0.0f;
    int    cur_g = -1;

    int r = r0;
    while (r < r1) {
        int m = min(32, r1 - r);
        int bi = batch[(lane < m) ? (r + lane) : r];
        int b0 = __shfl_sync(WARP_FULL, bi, 0);
        bool uni = __all_sync(WARP_FULL, bi == b0);

        if (uni && m == 32) {
            if (b0 != cur_g) {
                flush_seg(cur_g, lane, acc, cnt);
                acc = make_float4(0.f, 0.f, 0.f, 0.f);
                cnt = 0.0f;
                cur_g = b0;
            }
            const float4* p = x4 + (size_t)r * 32 + lane;
            #pragma unroll
            for (int i = 0; i < 32; ++i) {
                float4 v = __ldcs(p + (size_t)i * 32);   // streaming: no reuse
                acc.x += v.x; acc.y += v.y; acc.z += v.z; acc.w += v.w;
            }
            cnt += 32.0f;
            r += 32;
        } else {
            // slow path: true segment boundaries (or the final ragged tail)
            for (int i = 0; i < m; ++i) {
                int gi = __shfl_sync(WARP_FULL, bi, i);
                if (gi != cur_g) {
                    flush_seg(cur_g, lane, acc, cnt);
                    acc = make_float4(0.f, 0.f, 0.f, 0.f);
                    cnt = 0.0f;
                    cur_g = gi;
                }
                float4 v = __ldcs(&x4[(size_t)(r + i) * 32 + lane]);
                acc.x += v.x; acc.y += v.y; acc.z += v.z; acc.w += v.w;
                cnt += 1.0f;
            }
            r += m;
        }
    }
    flush_seg(cur_g, lane, acc, cnt);
}

// ---------------------------------------------------------------------------
// Kernel 2: per-graph mean + MLP head, PDL-overlapped.
// 128 blocks x 256 threads, 2 graphs per block (single wave). W1 staging and
// weight/bias loads run BEFORE cudaGridDependencySynchronize(), overlapping
// the reduce kernel's drain. Epilogue self-cleans accumulators.
// ---------------------------------------------------------------------------
__global__ __launch_bounds__(256) void mlp_kernel(
    const float* __restrict__ W1,   // [128, 64] row-major
    const float* __restrict__ b1,   // [64]
    const float* __restrict__ W2,   // [64, 1]
    const float* __restrict__ b2,   // [1]
    float* __restrict__ out)        // [G, 1]
{
    __shared__ float W1s[D * H];            // 32 KB
    __shared__ float mean[GPB][D];
    __shared__ float part[GPB][2][H];
    __shared__ float partial[GPB][2];

    const int tid = threadIdx.x;
    const int gl  = tid >> 7;               // graph-in-block 0..1
    const int s   = (tid >> 6) & 1;         // k-slice 0..1
    const int j   = tid & 63;               // hidden unit 0..63

    // ---- pre-dependency phase: stage weights (overlaps reduce drain) ----
    {
        const float4* w4 = (const float4*)W1;
        float4* s4 = (float4*)W1s;
        #pragma unroll
        for (int i = 0; i < 8; ++i)                    // 2048 float4 total
            s4[tid + i * 256] = __ldg(w4 + tid + i * 256);
    }

    // ---- wait for reduce kernel's writes to be visible ----
    cudaGridDependencySynchronize();

    // stage means: 256 threads cover 2 graphs x 128 dims
    {
        int gg = blockIdx.x * GPB + (tid >> 7);
        int d  = tid & 127;
        float c = g_counts[gg];
        float inv = (c > 0.0f) ? (1.0f / c) : 0.0f;
        mean[tid >> 7][d] = g_sums[gg * D + d] * inv;
        // self-clean for next replay (block owns its 2 graphs)
        g_sums[gg * D + d] = 0.0f;
        if (d == 0) g_counts[gg] = 0.0f;
    }
    __syncthreads();

    // partial dot: k in [64s, 64s+64)
    float h = 0.0f;
    #pragma unroll
    for (int k = 64 * s; k < 64 * s + 64; ++k)
        h = fmaf(mean[gl][k], W1s[k * H + j], h);      // broadcast + stride-1
    part[gl][s][j] = h;
    __syncthreads();

    // combine slices, relu, second layer (128 threads: gl' = tid>>6, j'=tid&63)
    if (tid < 128) {
        int gl2 = tid >> 6;
        int j2  = tid & 63;
        float hf = b1[j2] + part[gl2][0][j2] + part[gl2][1][j2];
        hf = fmaxf(hf, 0.0f);
        float p = hf * W2[j2];
        #pragma unroll
        for (int o = 16; o > 0; o >>= 1) p += __shfl_down_sync(WARP_FULL, p, o);
        if ((tid & 31) == 0) partial[gl2][(tid >> 5) & 1] = p;
    }
    __syncthreads();
    if (tid < GPB) out[blockIdx.x * GPB + tid] = partial[tid][0] + partial[tid][1] + b2[0];
}

// ---------------------------------------------------------------------------
extern "C" void kernel_launch(void* const* d_in, const int* in_sizes, int n_in,
                              void* d_out, int out_size) {
    const float* x     = (const float*)d_in[0];
    const int*   batch = (const int*)d_in[1];
    const float* W1    = (const float*)d_in[2];
    const float* b1    = (const float*)d_in[3];
    const float* W2    = (const float*)d_in[4];
    const float* b2    = (const float*)d_in[5];
    float*       out   = (float*)d_out;

    const int N = in_sizes[1];

    // single-wave streaming segment-sum: 592 CTAs x 8 warps (4 CTAs/SM).
    const int blocks = 592;
    const int warps_total = blocks * 8;                 // 4736
    int chunks = (N + 31) / 32;                          // 32-row chunks
    int chunks_base = chunks / warps_total;
    int chunks_rem  = chunks % warps_total;
    reduce_kernel<<<blocks, 256>>>((const float4*)x, batch, N,
                                   chunks_base, chunks_rem);

    // MLP head with programmatic dependent launch: placement + weight staging
    // overlap the reduce drain; gridDependencySynchronize gates g_sums reads.
    cudaLaunchConfig_t cfg = {};
    cfg.gridDim  = dim3(G / GPB, 1, 1);
    cfg.blockDim = dim3(256, 1, 1);
    cfg.dynamicSmemBytes = 0;
    cfg.stream = 0;
    cudaLaunchAttribute attrs[1];
    attrs[0].id = cudaLaunchAttributeProgrammaticStreamSerialization;
    attrs[0].val.programmaticStreamSerializationAllowed = 1;
    cfg.attrs = attrs;
    cfg.numAttrs = 1;
    cudaLaunchKernelEx(&cfg, mlp_kernel, W1, b1, W2, b2, out);
}